// round 8
// baseline (speedup 1.0000x reference)
#include <cuda_runtime.h>
#include <cuda_bf16.h>
#include <cstdint>
#include <cstddef>

// Problem constants
#define BB 2
#define TT 2048
#define CC 1024
#define HH 16
#define DD 64
#define NEGINF (-1e10f)

// ---------------------------------------------------------------------------
// Device-global scratch (no allocation allowed). q/k/v/y live ONLY as
// pre-split bf16 hi/lo pairs.
// ---------------------------------------------------------------------------
__device__ __nv_bfloat16 g_qh[(size_t)BB * HH * TT * DD];
__device__ __nv_bfloat16 g_ql[(size_t)BB * HH * TT * DD];
__device__ __nv_bfloat16 g_kh[(size_t)BB * HH * TT * DD];
__device__ __nv_bfloat16 g_kl[(size_t)BB * HH * TT * DD];
__device__ __nv_bfloat16 g_vh[(size_t)BB * HH * TT * DD];
__device__ __nv_bfloat16 g_vl[(size_t)BB * HH * TT * DD];
__device__ __nv_bfloat16 g_yh[(size_t)BB * TT * CC];
__device__ __nv_bfloat16 g_yl[(size_t)BB * TT * CC];

__device__ __nv_bfloat16 g_xh[(size_t)BB * TT * CC];
__device__ __nv_bfloat16 g_xl[(size_t)BB * TT * CC];
__device__ __nv_bfloat16 g_wah[(size_t)3 * CC * CC];
__device__ __nv_bfloat16 g_wal[(size_t)3 * CC * CC];
__device__ __nv_bfloat16 g_wph[(size_t)CC * CC];
__device__ __nv_bfloat16 g_wpl[(size_t)CC * CC];

// ---------------------------------------------------------------------------
// PTX helpers (sm_80+ — legal on plain sm_100 target)
// ---------------------------------------------------------------------------
__device__ __forceinline__ uint32_t smem_u32(const void* p) {
    return (uint32_t)__cvta_generic_to_shared(p);
}
__device__ __forceinline__ void cp16(uint32_t s, const void* g) {
    asm volatile("cp.async.cg.shared.global [%0], [%1], 16;" :: "r"(s), "l"(g));
}
__device__ __forceinline__ void cp_commit() {
    asm volatile("cp.async.commit_group;" ::: "memory");
}
template <int N>
__device__ __forceinline__ void cp_wait() {
    asm volatile("cp.async.wait_group %0;" :: "n"(N) : "memory");
}
__device__ __forceinline__ void ldmatrix_x4(uint32_t* r, uint32_t addr) {
    asm volatile("ldmatrix.sync.aligned.m8n8.x4.shared.b16 {%0,%1,%2,%3}, [%4];"
                 : "=r"(r[0]), "=r"(r[1]), "=r"(r[2]), "=r"(r[3]) : "r"(addr));
}
__device__ __forceinline__ void ldmatrix_x4_trans(uint32_t* r, uint32_t addr) {
    asm volatile("ldmatrix.sync.aligned.m8n8.x4.trans.shared.b16 {%0,%1,%2,%3}, [%4];"
                 : "=r"(r[0]), "=r"(r[1]), "=r"(r[2]), "=r"(r[3]) : "r"(addr));
}
__device__ __forceinline__ void mma_bf16(float* d, const uint32_t* a,
                                         const uint32_t* b) {
    asm volatile(
        "mma.sync.aligned.m16n8k16.row.col.f32.bf16.bf16.f32 "
        "{%0,%1,%2,%3}, {%4,%5,%6,%7}, {%8,%9}, {%0,%1,%2,%3};"
        : "+f"(d[0]), "+f"(d[1]), "+f"(d[2]), "+f"(d[3])
        : "r"(a[0]), "r"(a[1]), "r"(a[2]), "r"(a[3]), "r"(b[0]), "r"(b[1]));
}
// pack two f32 as bf16x2: first arg -> low half
__device__ __forceinline__ uint32_t pack_bf16(float lo, float hi) {
    uint32_t r;
    asm("cvt.rn.bf16x2.f32 %0, %1, %2;" : "=r"(r) : "f"(hi), "f"(lo));
    return r;
}

// ---------------------------------------------------------------------------
// Convert kernels: fp32 -> (bf16 hi, bf16 lo)
// ---------------------------------------------------------------------------
__global__ void split_kernel(const float* __restrict__ src,
                             __nv_bfloat16* __restrict__ hi,
                             __nv_bfloat16* __restrict__ lo, int n)
{
    int i = blockIdx.x * blockDim.x + threadIdx.x;
    if (i < n) {
        float v = src[i];
        __nv_bfloat16 h = __float2bfloat16(v);
        hi[i] = h;
        lo[i] = __float2bfloat16(v - __bfloat162float(h));
    }
}

__global__ void transpose_split_kernel(const float* __restrict__ src,
                                       __nv_bfloat16* __restrict__ hi,
                                       __nv_bfloat16* __restrict__ lo,
                                       int K, int N)
{
    __shared__ float tile[32][33];
    const int k0 = blockIdx.y * 32;
    const int n0 = blockIdx.x * 32;
    const int tx = threadIdx.x, ty = threadIdx.y;  // (32, 8)
#pragma unroll
    for (int i = ty; i < 32; i += 8)
        tile[i][tx] = src[(size_t)(k0 + i) * N + n0 + tx];
    __syncthreads();
#pragma unroll
    for (int i = ty; i < 32; i += 8) {
        float v = tile[tx][i];
        __nv_bfloat16 h = __float2bfloat16(v);
        size_t o = (size_t)(n0 + i) * K + k0 + tx;
        hi[o] = h;
        lo[o] = __float2bfloat16(v - __bfloat162float(h));
    }
}

// ---------------------------------------------------------------------------
// cp.async double-buffered mma.sync bf16 3-pass GEMM
// D[M,N] = A[M,K] @ B^T[N,K] + bias.  CTA tile 128x128, BK=32, 8 warps.
// Prefetch for ch+1 is issued+committed right after the barrier (full-chunk
// latency-hiding window), then both k-steps compute.
// ---------------------------------------------------------------------------
#define BK 32
#define LDS_ROW 40                 // 80B rows, 16B-aligned, conflict-free
#define G_BUF 10240                // 128*40*2
#define G_STAGE (4 * G_BUF)        // 40960
#define GEMM_SMEM (2 * G_STAGE)    // 81920

__device__ __forceinline__ void gemm_stage_load(
    uint32_t sb,
    const __nv_bfloat16* Ahi, const __nv_bfloat16* Alo,
    const __nv_bfloat16* Bhi, const __nv_bfloat16* Blo,
    int m0, int n0, int k0, int tid, int sub)
{
    const int K = CC;
    const int idx = sub * 256 + tid;
    const int r = idx >> 2;
    const int c = (idx & 3) * 8;
    const uint32_t so = (uint32_t)(r * LDS_ROW + c) * 2;
    const size_t goA = (size_t)(m0 + r) * K + k0 + c;
    const size_t goB = (size_t)(n0 + r) * K + k0 + c;
    cp16(sb + 0 * G_BUF + so, Ahi + goA);
    cp16(sb + 1 * G_BUF + so, Alo + goA);
    cp16(sb + 2 * G_BUF + so, Bhi + goB);
    cp16(sb + 3 * G_BUF + so, Blo + goB);
}

__global__ __launch_bounds__(256, 2) void tc_gemm_kernel(
    const __nv_bfloat16* __restrict__ Ahi, const __nv_bfloat16* __restrict__ Alo,
    const __nv_bfloat16* __restrict__ Bhi, const __nv_bfloat16* __restrict__ Blo,
    const float* __restrict__ bias, float* __restrict__ Cout,
    int N, int mode)
{
    extern __shared__ __align__(16) char dsm[];
    const uint32_t sb0 = smem_u32(dsm);

    const int tid = threadIdx.x;
    const int warp = tid >> 5;
    const int lane = tid & 31;
    const int warpM = warp >> 2;
    const int warpN = warp & 3;
    const int m0 = blockIdx.y * 128;
    const int n0 = blockIdx.x * 128;

    float acc[4][4][4];
#pragma unroll
    for (int mt = 0; mt < 4; mt++)
#pragma unroll
        for (int nt = 0; nt < 4; nt++)
#pragma unroll
            for (int i = 0; i < 4; i++) acc[mt][nt][i] = 0.0f;

    const int aRow = warpM * 64 + (lane & 15);
    const int aK   = (lane >> 4) * 8;
    const int bRow4 = warpN * 32 + (lane >> 4) * 8 + (lane & 7);
    const int bK4   = ((lane >> 3) & 1) * 8;

    const int NCH = CC / BK;   // 32

    gemm_stage_load(sb0, Ahi, Alo, Bhi, Blo, m0, n0, 0, tid, 0);
    gemm_stage_load(sb0, Ahi, Alo, Bhi, Blo, m0, n0, 0, tid, 1);
    cp_commit();

    for (int ch = 0; ch < NCH; ch++) {
        cp_wait<0>();
        __syncthreads();

        // prefetch next chunk NOW — full-chunk window to land
        if (ch + 1 < NCH) {
            const uint32_t pb = sb0 + ((ch + 1) & 1) * G_STAGE;
            gemm_stage_load(pb, Ahi, Alo, Bhi, Blo, m0, n0, (ch + 1) * BK, tid, 0);
            gemm_stage_load(pb, Ahi, Alo, Bhi, Blo, m0, n0, (ch + 1) * BK, tid, 1);
            cp_commit();
        }

        const uint32_t st = sb0 + (ch & 1) * G_STAGE;
        const uint32_t sa_hi = st, sa_lo = st + G_BUF;
        const uint32_t sb_hi = st + 2 * G_BUF, sb_lo = st + 3 * G_BUF;

#pragma unroll
        for (int ks = 0; ks < 2; ks++) {
            const int kk = ks * 16;
            uint32_t afh[4][4], afl[4][4], bfr[2][2][4];
#pragma unroll
            for (int mt = 0; mt < 4; mt++) {
                const uint32_t off = ((aRow + mt * 16) * LDS_ROW + aK + kk) * 2;
                ldmatrix_x4(afh[mt], sa_hi + off);
                ldmatrix_x4(afl[mt], sa_lo + off);
            }
#pragma unroll
            for (int bp = 0; bp < 2; bp++) {
                const uint32_t off = ((bRow4 + bp * 16) * LDS_ROW + bK4 + kk) * 2;
                ldmatrix_x4(bfr[0][bp], sb_hi + off);
                ldmatrix_x4(bfr[1][bp], sb_lo + off);
            }
#pragma unroll
            for (int mt = 0; mt < 4; mt++)
#pragma unroll
                for (int nt = 0; nt < 4; nt++) {
                    const uint32_t* bh = bfr[0][nt >> 1] + (nt & 1) * 2;
                    const uint32_t* bl = bfr[1][nt >> 1] + (nt & 1) * 2;
                    mma_bf16(acc[mt][nt], afh[mt], bh);
                    mma_bf16(acc[mt][nt], afh[mt], bl);
                    mma_bf16(acc[mt][nt], afl[mt], bh);
                }
        }
    }

    // epilogue
#pragma unroll
    for (int mt = 0; mt < 4; mt++) {
#pragma unroll
        for (int i = 0; i < 2; i++) {
            const int m = m0 + warpM * 64 + mt * 16 + (lane >> 2) + i * 8;
            const int b = m >> 11;
            const int t = m & 2047;
#pragma unroll
            for (int nt = 0; nt < 4; nt++) {
                const int n = n0 + warpN * 32 + nt * 8 + (lane & 3) * 2;
                const float v0 = acc[mt][nt][i * 2 + 0] + bias[n];
                const float v1 = acc[mt][nt][i * 2 + 1] + bias[n + 1];
                if (mode == 0) {
                    const int region = n >> 10;      // 0=q 1=k 2=v
                    const int cc = n & 1023;
                    const int h = cc >> 6;
                    const int dd = cc & 63;
                    __nv_bfloat16* dh = (region == 0) ? g_qh
                                      : (region == 1) ? g_kh : g_vh;
                    __nv_bfloat16* dl = (region == 0) ? g_ql
                                      : (region == 1) ? g_kl : g_vl;
                    const size_t o = (((size_t)b * HH + h) * TT + t) * DD + dd;
                    const float h0 = __bfloat162float(__float2bfloat16(v0));
                    const float h1 = __bfloat162float(__float2bfloat16(v1));
                    *(uint32_t*)(dh + o) = pack_bf16(v0, v1);
                    *(uint32_t*)(dl + o) = pack_bf16(v0 - h0, v1 - h1);
                } else {
                    float2 w; w.x = v0; w.y = v1;
                    *(float2*)(Cout + (size_t)m * N + n) = w;
                }
            }
        }
    }
}

// ---------------------------------------------------------------------------
// cp.async double-buffered tensor-core flash attention (hi/lo compensated).
// Grid: (T/128, B*H). Block: 256 threads. Single barrier per KV tile.
// ---------------------------------------------------------------------------
#define KVROW 72                     // 144B rows, conflict-free
#define A_BUF (64 * KVROW * 2)       // 9216
#define A_STAGE (4 * A_BUF + 256)    // 37120 (am tile at +36864)
#define ATTN_SMEM (2 * A_STAGE)      // 74240

__device__ __forceinline__ void attn_stage_load(
    uint32_t sb,
    const __nv_bfloat16* Kh, const __nv_bfloat16* Kl,
    const __nv_bfloat16* Vh, const __nv_bfloat16* Vl,
    const float* amp, int k0, int tid)
{
    const int r = tid >> 2;
    const int s2 = (tid & 3) * 2;
#pragma unroll
    for (int i = 0; i < 2; i++) {
        const int seg = s2 + i;
        const uint32_t so = (uint32_t)(r * KVROW + seg * 8) * 2;
        const size_t go = (size_t)(k0 + r) * DD + seg * 8;
        cp16(sb + 0 * A_BUF + so, Kh + go);
        cp16(sb + 1 * A_BUF + so, Kl + go);
        cp16(sb + 2 * A_BUF + so, Vh + go);
        cp16(sb + 3 * A_BUF + so, Vl + go);
    }
    if (tid < 16) cp16(sb + 4 * A_BUF + tid * 16, amp + k0 + tid * 4);
}

__global__ __launch_bounds__(256) void attn_tc_kernel(const float* __restrict__ am)
{
    extern __shared__ __align__(16) char dsm[];
    const uint32_t sb0 = smem_u32(dsm);

    const int tid = threadIdx.x;
    const int warp = tid >> 5;
    const int lane = tid & 31;
    const int g = lane >> 2;
    const int c = lane & 3;
    const int bh = blockIdx.y;
    const int b = bh >> 4;
    const int h = bh & 15;
    const int qtile = gridDim.x - 1 - blockIdx.x;   // heavy CTAs first
    const int q0 = qtile * 128;

    const int r1 = q0 + warp * 16 + g;
    const int r2 = r1 + 8;

    const __nv_bfloat16* Qh = g_qh + (size_t)bh * TT * DD;
    const __nv_bfloat16* Ql = g_ql + (size_t)bh * TT * DD;
    const __nv_bfloat16* Kh = g_kh + (size_t)bh * TT * DD;
    const __nv_bfloat16* Kl = g_kl + (size_t)bh * TT * DD;
    const __nv_bfloat16* Vh = g_vh + (size_t)bh * TT * DD;
    const __nv_bfloat16* Vl = g_vl + (size_t)bh * TT * DD;
    const float* amp = am + b * TT;

    // Q fragments straight from pre-split globals
    uint32_t qh[4][4], ql[4][4];
#pragma unroll
    for (int ks = 0; ks < 4; ks++) {
#pragma unroll
        for (int half = 0; half < 2; half++) {
            const int col = ks * 16 + half * 8 + c * 2;
            qh[ks][half * 2 + 0] = *(const uint32_t*)(Qh + (size_t)r1 * DD + col);
            qh[ks][half * 2 + 1] = *(const uint32_t*)(Qh + (size_t)r2 * DD + col);
            ql[ks][half * 2 + 0] = *(const uint32_t*)(Ql + (size_t)r1 * DD + col);
            ql[ks][half * 2 + 1] = *(const uint32_t*)(Ql + (size_t)r2 * DD + col);
        }
    }

    float o[8][4];
#pragma unroll
    for (int nt = 0; nt < 8; nt++)
#pragma unroll
        for (int i = 0; i < 4; i++) o[nt][i] = 0.0f;
    float m0v = -1e30f, m1v = -1e30f;
    float l0 = 0.0f, l1 = 0.0f;

    const int g4 = lane >> 3;
    const int l8 = lane & 7;

    const int nkv = 2 * (qtile + 1);
    attn_stage_load(sb0, Kh, Kl, Vh, Vl, amp, 0, tid);
    cp_commit();

    for (int kt = 0; kt < nkv; kt++) {
        const int k0 = kt * 64;
        cp_wait<0>();
        __syncthreads();

        const uint32_t st = sb0 + (kt & 1) * A_STAGE;
        const uint32_t skh = st, skl = st + A_BUF;
        const uint32_t svh = st + 2 * A_BUF, svl = st + 3 * A_BUF;
        const float* amS = (const float*)(dsm + (kt & 1) * A_STAGE + 4 * A_BUF);
        const bool needCausal = (kt >= 2 * qtile);

        if (kt + 1 < nkv)
            attn_stage_load(sb0 + ((kt + 1) & 1) * A_STAGE,
                            Kh, Kl, Vh, Vl, amp, (kt + 1) * 64, tid);
        cp_commit();

        // --- S = Q @ K^T (3-term)
        float s[8][4];
#pragma unroll
        for (int nt = 0; nt < 8; nt++)
#pragma unroll
            for (int i = 0; i < 4; i++) s[nt][i] = 0.0f;

#pragma unroll
        for (int ks = 0; ks < 4; ks++) {
#pragma unroll
            for (int nt2 = 0; nt2 < 4; nt2++) {
                const uint32_t off =
                    ((nt2 * 16 + (g4 >> 1) * 8 + l8) * KVROW +
                     ks * 16 + (g4 & 1) * 8) * 2;
                uint32_t bhf[4], blf[4];
                ldmatrix_x4(bhf, skh + off);
                ldmatrix_x4(blf, skl + off);
                mma_bf16(s[nt2 * 2 + 0], qh[ks], bhf);
                mma_bf16(s[nt2 * 2 + 1], qh[ks], bhf + 2);
                mma_bf16(s[nt2 * 2 + 0], qh[ks], blf);
                mma_bf16(s[nt2 * 2 + 1], qh[ks], blf + 2);
                mma_bf16(s[nt2 * 2 + 0], ql[ks], bhf);
                mma_bf16(s[nt2 * 2 + 1], ql[ks], bhf + 2);
            }
        }

        // --- scale + masks
#pragma unroll
        for (int nt = 0; nt < 8; nt++) {
            const int colb = nt * 8 + c * 2;
            const float a0 = amS[colb] * NEGINF;
            const float a1 = amS[colb + 1] * NEGINF;
            s[nt][0] = s[nt][0] * 0.125f + a0;
            s[nt][1] = s[nt][1] * 0.125f + a1;
            s[nt][2] = s[nt][2] * 0.125f + a0;
            s[nt][3] = s[nt][3] * 0.125f + a1;
            if (needCausal) {
                const int kg0 = k0 + colb;
                if (kg0 > r1)     s[nt][0] = -1e30f;
                if (kg0 + 1 > r1) s[nt][1] = -1e30f;
                if (kg0 > r2)     s[nt][2] = -1e30f;
                if (kg0 + 1 > r2) s[nt][3] = -1e30f;
            }
        }

        // --- online softmax
        float t0 = -1e30f, t1 = -1e30f;
#pragma unroll
        for (int nt = 0; nt < 8; nt++) {
            t0 = fmaxf(t0, fmaxf(s[nt][0], s[nt][1]));
            t1 = fmaxf(t1, fmaxf(s[nt][2], s[nt][3]));
        }
        t0 = fmaxf(t0, __shfl_xor_sync(0xffffffffu, t0, 1));
        t0 = fmaxf(t0, __shfl_xor_sync(0xffffffffu, t0, 2));
        t1 = fmaxf(t1, __shfl_xor_sync(0xffffffffu, t1, 1));
        t1 = fmaxf(t1, __shfl_xor_sync(0xffffffffu, t1, 2));

        const float mn0 = fmaxf(m0v, t0);
        const float mn1 = fmaxf(m1v, t1);
        const float cr0 = __expf(m0v - mn0);
        const float cr1 = __expf(m1v - mn1);
        m0v = mn0; m1v = mn1;

        float s0 = 0.0f, s1 = 0.0f;
#pragma unroll
        for (int nt = 0; nt < 8; nt++) {
            s[nt][0] = __expf(s[nt][0] - mn0);
            s[nt][1] = __expf(s[nt][1] - mn0);
            s[nt][2] = __expf(s[nt][2] - mn1);
            s[nt][3] = __expf(s[nt][3] - mn1);
            s0 += s[nt][0] + s[nt][1];
            s1 += s[nt][2] + s[nt][3];
            o[nt][0] *= cr0; o[nt][1] *= cr0;
            o[nt][2] *= cr1; o[nt][3] *= cr1;
        }
        s0 += __shfl_xor_sync(0xffffffffu, s0, 1);
        s0 += __shfl_xor_sync(0xffffffffu, s0, 2);
        s1 += __shfl_xor_sync(0xffffffffu, s1, 1);
        s1 += __shfl_xor_sync(0xffffffffu, s1, 2);
        l0 = l0 * cr0 + s0;
        l1 = l1 * cr1 + s1;

        // --- O += P @ V (3-term)
#pragma unroll
        for (int j = 0; j < 4; j++) {
            uint32_t pfh[4], pfl[4];
            {
                const float p00 = s[2 * j][0],     p01 = s[2 * j][1];
                const float p10 = s[2 * j][2],     p11 = s[2 * j][3];
                const float p20 = s[2 * j + 1][0], p21 = s[2 * j + 1][1];
                const float p30 = s[2 * j + 1][2], p31 = s[2 * j + 1][3];
                const float h00 = __bfloat162float(__float2bfloat16(p00));
                const float h01 = __bfloat162float(__float2bfloat16(p01));
                const float h10 = __bfloat162float(__float2bfloat16(p10));
                const float h11 = __bfloat162float(__float2bfloat16(p11));
                const float h20 = __bfloat162float(__float2bfloat16(p20));
                const float h21 = __bfloat162float(__float2bfloat16(p21));
                const float h30 = __bfloat162float(__float2bfloat16(p30));
                const float h31 = __bfloat162float(__float2bfloat16(p31));
                pfh[0] = pack_bf16(p00, p01);
                pfh[1] = pack_bf16(p10, p11);
                pfh[2] = pack_bf16(p20, p21);
                pfh[3] = pack_bf16(p30, p31);
                pfl[0] = pack_bf16(p00 - h00, p01 - h01);
                pfl[1] = pack_bf16(p10 - h10, p11 - h11);
                pfl[2] = pack_bf16(p20 - h20, p21 - h21);
                pfl[3] = pack_bf16(p30 - h30, p31 - h31);
            }
#pragma unroll
            for (int nt2 = 0; nt2 < 4; nt2++) {
                const uint32_t off =
                    ((16 * j + (g4 & 1) * 8 + l8) * KVROW +
                     nt2 * 16 + (g4 >> 1) * 8) * 2;
                uint32_t vhf[4], vlf[4];
                ldmatrix_x4_trans(vhf, svh + off);
                ldmatrix_x4_trans(vlf, svl + off);
                mma_bf16(o[nt2 * 2 + 0], pfh, vhf);
                mma_bf16(o[nt2 * 2 + 1], pfh, vhf + 2);
                mma_bf16(o[nt2 * 2 + 0], pfh, vlf);
                mma_bf16(o[nt2 * 2 + 1], pfh, vlf + 2);
                mma_bf16(o[nt2 * 2 + 0], pfl, vhf);
                mma_bf16(o[nt2 * 2 + 1], pfl, vhf + 2);
            }
        }
    }

    // --- epilogue: normalize, split, write g_yh/g_yl
    const float i0 = 1.0f / l0;
    const float i1 = 1.0f / l1;
    __nv_bfloat16* Yh1 = g_yh + (size_t)(b * TT + r1) * CC + h * DD;
    __nv_bfloat16* Yl1 = g_yl + (size_t)(b * TT + r1) * CC + h * DD;
    __nv_bfloat16* Yh2 = g_yh + (size_t)(b * TT + r2) * CC + h * DD;
    __nv_bfloat16* Yl2 = g_yl + (size_t)(b * TT + r2) * CC + h * DD;
#pragma unroll
    for (int nt = 0; nt < 8; nt++) {
        const int col = nt * 8 + c * 2;
        const float w0x = o[nt][0] * i0, w0y = o[nt][1] * i0;
        const float w1x = o[nt][2] * i1, w1y = o[nt][3] * i1;
        const float h0x = __bfloat162float(__float2bfloat16(w0x));
        const float h0y = __bfloat162float(__float2bfloat16(w0y));
        const float h1x = __bfloat162float(__float2bfloat16(w1x));
        const float h1y = __bfloat162float(__float2bfloat16(w1y));
        *(uint32_t*)(Yh1 + col) = pack_bf16(w0x, w0y);
        *(uint32_t*)(Yl1 + col) = pack_bf16(w0x - h0x, w0y - h0y);
        *(uint32_t*)(Yh2 + col) = pack_bf16(w1x, w1y);
        *(uint32_t*)(Yl2 + col) = pack_bf16(w1x - h1x, w1y - h1y);
    }
}

// ---------------------------------------------------------------------------
extern "C" void kernel_launch(void* const* d_in, const int* in_sizes, int n_in,
                              void* d_out, int out_size)
{
    (void)in_sizes; (void)n_in; (void)out_size;
    const float* x  = (const float*)d_in[0];   // [B,T,C]
    const float* am = (const float*)d_in[1];   // [B,T]
    const float* Wa = (const float*)d_in[2];   // [C,3C]
    const float* ba = (const float*)d_in[3];   // [3C]
    const float* Wp = (const float*)d_in[4];   // [C,C]
    const float* bp = (const float*)d_in[5];   // [C]
    float* out = (float*)d_out;                // [B,T,C]

    cudaFuncSetAttribute(tc_gemm_kernel,
                         cudaFuncAttributeMaxDynamicSharedMemorySize, GEMM_SMEM);
    cudaFuncSetAttribute(attn_tc_kernel,
                         cudaFuncAttributeMaxDynamicSharedMemorySize, ATTN_SMEM);

    __nv_bfloat16 *xh, *xl, *yh, *yl, *wah, *wal, *wph, *wpl;
    cudaGetSymbolAddress((void**)&xh,  g_xh);
    cudaGetSymbolAddress((void**)&xl,  g_xl);
    cudaGetSymbolAddress((void**)&yh,  g_yh);
    cudaGetSymbolAddress((void**)&yl,  g_yl);
    cudaGetSymbolAddress((void**)&wah, g_wah);
    cudaGetSymbolAddress((void**)&wal, g_wal);
    cudaGetSymbolAddress((void**)&wph, g_wph);
    cudaGetSymbolAddress((void**)&wpl, g_wpl);

    const int M = BB * TT;          // 4096

    // 0) operand conversion
    split_kernel<<<(M * CC) / 256, 256>>>(x, xh, xl, M * CC);
    transpose_split_kernel<<<dim3(3 * CC / 32, CC / 32), dim3(32, 8)>>>(
        Wa, wah, wal, CC, 3 * CC);
    transpose_split_kernel<<<dim3(CC / 32, CC / 32), dim3(32, 8)>>>(
        Wp, wph, wpl, CC, CC);

    // 1) QKV projection -> pre-split q/k/v hi/lo [B,H,T,D]
    tc_gemm_kernel<<<dim3(3 * CC / 128, M / 128), 256, GEMM_SMEM>>>(
        xh, xl, wah, wal, ba, nullptr, 3 * CC, 0);

    // 2) flash attention -> pre-split y hi/lo [B,T,C]
    attn_tc_kernel<<<dim3(TT / 128, BB * HH), 256, ATTN_SMEM>>>(am);

    // 3) output projection -> d_out fp32
    tc_gemm_kernel<<<dim3(CC / 128, M / 128), 256, GEMM_SMEM>>>(
        yh, yl, wph, wpl, bp, out, CC, 1);
}